// round 5
// baseline (speedup 1.0000x reference)
#include <cuda_runtime.h>
#include <cuda_bf16.h>

// ============================================================================
// SiblingNDMV — algorithmic collapse: all factors depend only on POS tag
// (34 tags + 1 no-sib), so attach/decision/root reduce to small log-softmaxed
// tables + a big gather-write (145 MB total output).
// ============================================================================

#define BN      64      // batch
#define NN      64      // sequence length
#define PP      256     // hidden
#define CC      34      // child classes
#define NTS     35      // sibling states: 34 tags + no_sib (index 34)
#define MM      65      // n+1
#define RA_     128
#define RD_     128
#define RRANK   64
#define NROWS   106     // 34 parent + 35 sib + 34 child + 1 root + 2 dec

// ----- device scratch (static allocation; no cudaMalloc allowed) -----
__device__ float g_PRE[NROWS * PP];
__device__ __align__(16) float g_FP[CC * 4 * RA_];
__device__ __align__(16) float g_FC[CC * 4 * RA_];
__device__ __align__(16) float g_FS[NTS * 4 * RA_];
__device__ __align__(16) float g_GP[CC * 4 * RD_];
__device__ __align__(16) float g_GS[NTS * 4 * RD_];
__device__ __align__(16) float g_GD[2 * 4 * RD_];
__device__ __align__(16) float g_RRv[4 * RRANK];
__device__ __align__(16) float g_RCv[CC * 4 * RRANK];
__device__ __align__(16) float g_ALS[CC * CC * 2 * NTS * 2]; // [tp][c][d][ts][v]
__device__ __align__(16) float g_DLS[CC * NTS * 2 * 2 * 2];  // [tp][ts][d][v][k]

// ============================================================================
// K1: pre-activation rows: PRE[r][q] = x_r @ W + b  (106 rows)
//   r in [0,34)   : parent tag t      x=pos_emb[t],     W=Wp
//   r in [34,68)  : sib tag t=r-34    x=pos_emb[t],     W=Ws
//   r == 68       : no_sib            PRE = pos_emb[35] (raw, no matmul!)
//   r in [69,103) : child c=r-69      x=pos_emb[1+c],   W=Wc
//   r == 103      : root              x=root_emb,       W=Wr
//   r in [104,106): dec k=r-104       x=decision_emb[k],W=Wd
// ============================================================================
__global__ void k_pre(const float* __restrict__ pos_emb,
                      const float* __restrict__ root_emb,
                      const float* __restrict__ dec_emb,
                      const float* __restrict__ Wp, const float* __restrict__ bp,
                      const float* __restrict__ Ws, const float* __restrict__ bs,
                      const float* __restrict__ Wc, const float* __restrict__ bc,
                      const float* __restrict__ Wr, const float* __restrict__ br,
                      const float* __restrict__ Wd, const float* __restrict__ bd) {
    int r = blockIdx.x, q = threadIdx.x;
    if (r == 68) { g_PRE[r * PP + q] = pos_emb[35 * PP + q]; return; }
    __shared__ float xs[PP];
    const float *x, *W, *bias;
    if (r < 34)       { x = pos_emb + r * PP;            W = Wp; bias = bp; }
    else if (r < 68)  { x = pos_emb + (r - 34) * PP;     W = Ws; bias = bs; }
    else if (r < 103) { x = pos_emb + (r - 69 + 1) * PP; W = Wc; bias = bc; }
    else if (r == 103){ x = root_emb;                    W = Wr; bias = br; }
    else              { x = dec_emb + (r - 104) * PP;    W = Wd; bias = bd; }
    xs[q] = x[q];
    __syncthreads();
    float acc = bias[q];
    #pragma unroll 8
    for (int p = 0; p < PP; p++) acc = fmaf(xs[p], W[p * PP + q], acc);
    g_PRE[r * PP + q] = acc;
}

// ============================================================================
// K2: SkipConnectEncoder h = pre + relu(pre @ W_enc[d,v] + b_enc[d,v]),
//     then project h straight into the factor tables (fp/gp, fs/gs, fc/rc,
//     rr, gd). One block per (row, dv).
// ============================================================================
__global__ void k_enc(const float* __restrict__ W_enc, const float* __restrict__ b_enc,
                      const float* __restrict__ Ua1, const float* __restrict__ Ua2,
                      const float* __restrict__ Ua3, const float* __restrict__ Ud1,
                      const float* __restrict__ Ud2, const float* __restrict__ Ud3,
                      const float* __restrict__ Ur1, const float* __restrict__ Ur2) {
    int r = blockIdx.x >> 2, dv = blockIdx.x & 3, q = threadIdx.x;
    __shared__ float pre_s[PP];
    __shared__ float h_s[PP];
    pre_s[q] = g_PRE[r * PP + q];
    __syncthreads();
    float acc = b_enc[dv * PP + q];
    const float* W = W_enc + (size_t)dv * PP * PP;
    #pragma unroll 8
    for (int p = 0; p < PP; p++) acc = fmaf(pre_s[p], W[p * PP + q], acc);
    h_s[q] = pre_s[q] + fmaxf(acc, 0.f);
    __syncthreads();

    if (r < 34) {                       // parent: fp (Ua1,128) + gp (Ud1,128)
        int t = r;
        if (q < 128) {
            float a = 0.f;
            #pragma unroll 8
            for (int p = 0; p < PP; p++) a = fmaf(h_s[p], Ua1[p * 128 + q], a);
            g_FP[(t * 4 + dv) * 128 + q] = a;
        } else {
            int u = q - 128; float a = 0.f;
            #pragma unroll 8
            for (int p = 0; p < PP; p++) a = fmaf(h_s[p], Ud1[p * 128 + u], a);
            g_GP[(t * 4 + dv) * 128 + u] = a;
        }
    } else if (r < 69) {                // sib: fs (Ua3) + gs (Ud2)
        int ts = r - 34;
        if (q < 128) {
            float a = 0.f;
            #pragma unroll 8
            for (int p = 0; p < PP; p++) a = fmaf(h_s[p], Ua3[p * 128 + q], a);
            g_FS[(ts * 4 + dv) * 128 + q] = a;
        } else {
            int u = q - 128; float a = 0.f;
            #pragma unroll 8
            for (int p = 0; p < PP; p++) a = fmaf(h_s[p], Ud2[p * 128 + u], a);
            g_GS[(ts * 4 + dv) * 128 + u] = a;
        }
    } else if (r < 103) {               // child: fc (Ua2,128) + rc (Ur2,64)
        int c = r - 69;
        if (q < 128) {
            float a = 0.f;
            #pragma unroll 8
            for (int p = 0; p < PP; p++) a = fmaf(h_s[p], Ua2[p * 128 + q], a);
            g_FC[(c * 4 + dv) * 128 + q] = a;
        } else if (q < 192) {
            int u = q - 128; float a = 0.f;
            #pragma unroll 8
            for (int p = 0; p < PP; p++) a = fmaf(h_s[p], Ur2[p * 64 + u], a);
            g_RCv[(c * 4 + dv) * 64 + u] = a;
        }
    } else if (r == 103) {              // root: rr (Ur1,64)
        if (q < 64) {
            float a = 0.f;
            #pragma unroll 8
            for (int p = 0; p < PP; p++) a = fmaf(h_s[p], Ur1[p * 64 + q], a);
            g_RRv[dv * 64 + q] = a;
        }
    } else {                            // dec: gd (Ud3,128)
        int k = r - 104;
        if (q < 128) {
            float a = 0.f;
            #pragma unroll 8
            for (int p = 0; p < PP; p++) a = fmaf(h_s[p], Ud3[p * 128 + q], a);
            g_GD[(k * 4 + dv) * 128 + q] = a;
        }
    }
}

// ============================================================================
// K3: attach table A[tp,c,ts,d,v] = sum_r fp*fc*fs, fused log-softmax over c.
//     One block per (tp, dv). Smem padded stride 129 -> conflict-free.
// ============================================================================
__global__ void k_attach_table() {
    int tp = blockIdx.x >> 2, dv = blockIdx.x & 3;
    int d = dv >> 1, v = dv & 1;
    int tid = threadIdx.x;
    __shared__ float fp_s[128];
    __shared__ float fc_s[CC * 129];
    __shared__ float fs_s[NTS * 129];
    __shared__ float a_s[CC * NTS];
    __shared__ float lse_s[NTS];
    if (tid < 128) fp_s[tid] = g_FP[(tp * 4 + dv) * 128 + tid];
    for (int i = tid; i < CC * 128; i += 256) {
        int c = i >> 7, rr = i & 127;
        fc_s[c * 129 + rr] = g_FC[(c * 4 + dv) * 128 + rr];
    }
    for (int i = tid; i < NTS * 128; i += 256) {
        int ts = i >> 7, rr = i & 127;
        fs_s[ts * 129 + rr] = g_FS[(ts * 4 + dv) * 128 + rr];
    }
    __syncthreads();
    for (int e = tid; e < CC * NTS; e += 256) {
        int c = e / NTS, ts = e % NTS;
        float s = 0.f;
        #pragma unroll 8
        for (int rr = 0; rr < 128; rr++)
            s = fmaf(fp_s[rr] * fc_s[c * 129 + rr], fs_s[ts * 129 + rr], s);
        a_s[e] = s;
    }
    __syncthreads();
    if (tid < NTS) {
        float mx = -1e30f;
        for (int c = 0; c < CC; c++) mx = fmaxf(mx, a_s[c * NTS + tid]);
        float se = 0.f;
        for (int c = 0; c < CC; c++) se += __expf(a_s[c * NTS + tid] - mx);
        lse_s[tid] = mx + __logf(se);
    }
    __syncthreads();
    for (int e = tid; e < CC * NTS; e += 256) {
        int c = e / NTS, ts = e % NTS;
        g_ALS[(((tp * CC + c) * 2 + d) * NTS + ts) * 2 + v] = a_s[e] - lse_s[ts];
    }
}

// ============================================================================
// K4: decision table D[tp,ts,d,v,k] + log-softmax over k (pairwise).
// ============================================================================
__global__ void k_dec_table() {
    int tp = blockIdx.x;
    int e = threadIdx.x;
    if (e >= NTS * 4) return;
    int ts = e >> 2, dv = e & 3;
    const float* gp = g_GP + (tp * 4 + dv) * 128;
    const float* gs = g_GS + (ts * 4 + dv) * 128;
    const float* g0 = g_GD + (0 * 4 + dv) * 128;
    const float* g1 = g_GD + (1 * 4 + dv) * 128;
    float s0 = 0.f, s1 = 0.f;
    #pragma unroll 8
    for (int r = 0; r < 128; r++) {
        float pg = gp[r] * gs[r];
        s0 = fmaf(pg, g0[r], s0);
        s1 = fmaf(pg, g1[r], s1);
    }
    float mx = fmaxf(s0, s1);
    float lse = mx + __logf(__expf(s0 - mx) + __expf(s1 - mx));
    int base = ((tp * NTS + ts) * 4 + dv) * 2;
    g_DLS[base + 0] = s0 - lse;
    g_DLS[base + 1] = s1 - lse;
}

// ============================================================================
// K5: root table (34 entries, log-softmax) + [B,N] root output gather.
// ============================================================================
__global__ void k_root(const int* __restrict__ pos_tag, float* __restrict__ out_root) {
    __shared__ float rs[CC];
    __shared__ float lse_sh;
    int tid = threadIdx.x;
    if (tid < CC) {
        float s = 0.f;
        for (int dv = 0; dv < 4; dv++) {
            const float* rr = g_RRv + dv * RRANK;
            const float* rc = g_RCv + (tid * 4 + dv) * RRANK;
            #pragma unroll 8
            for (int r = 0; r < RRANK; r++) s = fmaf(rr[r], rc[r], s);
        }
        rs[tid] = s;
    }
    __syncthreads();
    if (tid == 0) {
        float mx = -1e30f;
        for (int c = 0; c < CC; c++) mx = fmaxf(mx, rs[c]);
        float se = 0.f;
        for (int c = 0; c < CC; c++) se += __expf(rs[c] - mx);
        lse_sh = mx + __logf(se);
    }
    __syncthreads();
    for (int i = tid; i < BN * NN; i += blockDim.x) {
        int c = pos_tag[i] - 1; if (c < 0) c = 0;
        out_root[i] = rs[c] - lse_sh;
    }
}

// ============================================================================
// K6: attach output gather: [b,i,j,m,v] -> one float2 (v pair) per thread.
//     17,039,360 float2 = 136.3 MB fully-contiguous stores.
// ============================================================================
__global__ void k_attach_out(const int* __restrict__ pos_tag, float2* __restrict__ out) {
    int idx = blockIdx.x * 256 + threadIdx.x;   // exact grid: 66560*256
    int m   = idx % MM;
    int t   = idx / MM;                          // (b*64+i)*64 + j
    int j   = t & 63;
    int bi  = t >> 6;                            // b*64 + i
    int i   = bi & 63;
    int b64 = bi & ~63;                          // b*64
    if (j == i) { out[idx] = make_float2(0.f, 0.f); return; }
    int tp = __ldg(&pos_tag[bi]);
    int c  = __ldg(&pos_tag[b64 + j]) - 1; if (c < 0) c = 0;
    int d  = (j < i) ? 0 : 1;
    int ts = (m == 0) ? 34 : __ldg(&pos_tag[b64 + m - 1]);
    const float2* src = reinterpret_cast<const float2*>(g_ALS);
    out[idx] = src[((tp * CC + c) * 2 + d) * NTS + ts];
}

// ============================================================================
// K7: decision output gather: [b,i,m,(d,v,k)] -> 8 floats = 2x float4.
// ============================================================================
__global__ void k_dec_out(const int* __restrict__ pos_tag, float4* __restrict__ out) {
    int idx = blockIdx.x * 256 + threadIdx.x;   // exact grid: 1040*256 = 266240
    int m  = idx % MM;
    int bi = idx / MM;
    int b64 = bi & ~63;
    int tp = __ldg(&pos_tag[bi]);
    int ts = (m == 0) ? 34 : __ldg(&pos_tag[b64 + m - 1]);
    const float4* src = reinterpret_cast<const float4*>(g_DLS);
    int s = (tp * NTS + ts) * 2;
    out[idx * 2 + 0] = src[s + 0];
    out[idx * 2 + 1] = src[s + 1];
}

// ============================================================================
extern "C" void kernel_launch(void* const* d_in, const int* in_sizes, int n_in,
                              void* d_out, int out_size) {
    const int*   pos_tag = (const int*)  d_in[0];
    const float* pos_emb = (const float*)d_in[1];
    const float* root_emb= (const float*)d_in[2];
    const float* dec_emb = (const float*)d_in[3];
    const float* Wp = (const float*)d_in[4];  const float* bp = (const float*)d_in[5];
    const float* Ws = (const float*)d_in[6];  const float* bs = (const float*)d_in[7];
    const float* Wc = (const float*)d_in[8];  const float* bc = (const float*)d_in[9];
    const float* Wr = (const float*)d_in[10]; const float* br = (const float*)d_in[11];
    const float* Wd = (const float*)d_in[12]; const float* bd = (const float*)d_in[13];
    const float* W_enc = (const float*)d_in[14];
    const float* b_enc = (const float*)d_in[15];
    const float* Ua1 = (const float*)d_in[16];
    const float* Ua2 = (const float*)d_in[17];
    const float* Ua3 = (const float*)d_in[18];
    const float* Ud1 = (const float*)d_in[19];
    const float* Ud2 = (const float*)d_in[20];
    const float* Ud3 = (const float*)d_in[21];
    const float* Ur1 = (const float*)d_in[22];
    const float* Ur2 = (const float*)d_in[23];

    float* out = (float*)d_out;
    float* out_attach = out;                                   // 34,078,720
    float* out_dec    = out + 34078720;                        //  2,129,920
    float* out_root   = out + 34078720 + 2129920;              //      4,096

    k_pre<<<NROWS, 256>>>(pos_emb, root_emb, dec_emb,
                          Wp, bp, Ws, bs, Wc, bc, Wr, br, Wd, bd);
    k_enc<<<NROWS * 4, 256>>>(W_enc, b_enc, Ua1, Ua2, Ua3, Ud1, Ud2, Ud3, Ur1, Ur2);
    k_attach_table<<<CC * 4, 256>>>();
    k_dec_table<<<CC, 160>>>();
    k_root<<<1, 256>>>(pos_tag, out_root);
    k_attach_out<<<66560, 256>>>(pos_tag, (float2*)out_attach);
    k_dec_out<<<1040, 256>>>(pos_tag, (float4*)out_dec);
}